// round 6
// baseline (speedup 1.0000x reference)
#include <cuda_runtime.h>
#include <cuda_bf16.h>
#include <stdint.h>

#define N_TOKENS_TOTAL 16384
#define D_PROJ 1024
#define EMB_SCALE 32.0f
#define MAX_TILES 136      // sum ceil(cnt_c/128) <= 128+3
#define NTHREADS 384       // 8 consumer warps + 4 producer warps

// ---------------- scratch ----------------
__device__ int g_cnt[4];
__device__ int g_tok[4][N_TOKENS_TOTAL];
__device__ int g_loc[4][N_TOKENS_TOTAL];
__device__ int g_tile_c[MAX_TILES];
__device__ int g_tile_m0[MAX_TILES];
__device__ int g_total_tiles;

__constant__ int c_K[4] = {1024, 256, 64, 16};

// ---------------- helpers ----------------
__device__ __forceinline__ uint32_t smem_u32(const void* p) {
    uint32_t a;
    asm("{ .reg .u64 t; cvta.to.shared.u64 t, %1; cvt.u32.u64 %0, t; }" : "=r"(a) : "l"(p));
    return a;
}
__device__ __forceinline__ void ldsm4(uint32_t* r, uint32_t addr) {
    asm volatile("ldmatrix.sync.aligned.m8n8.x4.shared.b16 {%0,%1,%2,%3}, [%4];"
                 : "=r"(r[0]), "=r"(r[1]), "=r"(r[2]), "=r"(r[3]) : "r"(addr));
}
__device__ __forceinline__ void mma_bf16(float* c, const uint32_t* a,
                                         uint32_t b0, uint32_t b1) {
    asm volatile(
        "mma.sync.aligned.m16n8k16.row.col.f32.bf16.bf16.f32 "
        "{%0,%1,%2,%3}, {%4,%5,%6,%7}, {%8,%9}, {%0,%1,%2,%3};"
        : "+f"(c[0]), "+f"(c[1]), "+f"(c[2]), "+f"(c[3])
        : "r"(a[0]), "r"(a[1]), "r"(a[2]), "r"(a[3]), "r"(b0), "r"(b1));
}
#define BAR_SYNC(id)   asm volatile("bar.sync %0, %1;"   :: "r"(id), "r"(NTHREADS) : "memory")
#define BAR_ARRIVE(id) asm volatile("bar.arrive %0, %1;" :: "r"(id), "r"(NTHREADS) : "memory")
// barrier ids: FULL[b] = 1+b, EMPTY[b] = 3+b

__device__ __forceinline__ uint32_t swz(uint32_t base, int row, int kbyte) {
    return base + (((uint32_t)(row * 128 + kbyte)) ^ (uint32_t)((row & 7) << 4));
}
__device__ __forceinline__ void split2(float2 f, uint32_t& hi, uint32_t& lo) {
    __nv_bfloat162 h = __float22bfloat162_rn(f);
    float2 hf = __bfloat1622float2(h);
    float2 r = make_float2(f.x - hf.x, f.y - hf.y);
    __nv_bfloat162 l = __float22bfloat162_rn(r);
    hi = *reinterpret_cast<uint32_t*>(&h);
    lo = *reinterpret_cast<uint32_t*>(&l);
}
__device__ __forceinline__ void split8(float4 f0, float4 f1, uint4& hi, uint4& lo) {
    split2(make_float2(f0.x, f0.y), hi.x, lo.x);
    split2(make_float2(f0.z, f0.w), hi.y, lo.y);
    split2(make_float2(f1.x, f1.y), hi.z, lo.z);
    split2(make_float2(f1.z, f1.w), hi.w, lo.w);
}

// ---------------- small kernels ----------------
__global__ void zero_kernel() {
    if (threadIdx.x < 4) g_cnt[threadIdx.x] = 0;
}
__global__ void bucket_kernel(const int* __restrict__ inp, int n) {
    int t = blockIdx.x * blockDim.x + threadIdx.x;
    if (t >= n) return;
    int v = inp[t];
    int c, l;
    if (v < 20000)       { c = 0; l = 0; }
    else if (v < 40000)  { c = 1; l = 20000; }
    else if (v < 200000) { c = 2; l = 40000; }
    else                 { c = 3; l = 200000; }
    int p = atomicAdd(&g_cnt[c], 1);
    g_tok[c][p] = t;
    g_loc[c][p] = v - l;
}
__global__ void plan_kernel() {
    __shared__ int offs[5];
    if (threadIdx.x == 0) {
        offs[0] = 0;
        for (int c = 0; c < 4; c++) offs[c + 1] = offs[c] + ((g_cnt[c] + 127) >> 7);
        g_total_tiles = offs[4];
    }
    __syncthreads();
    const int total = offs[4];
    for (int i = threadIdx.x; i < total; i += blockDim.x) {
        int c = 0;
        while (i >= offs[c + 1]) c++;
        g_tile_c[i] = c;
        g_tile_m0[i] = (i - offs[c]) << 7;
    }
}

// ---------------- fused pipelined GEMM ----------------
// smem: 2 buffers x (Ahi,Alo,Bhi,Blo)[128][64] bf16 = 2 x 64KB.
#define BUF_STRIDE 65536
#define OFF_AHI 0
#define OFF_ALO 16384
#define OFF_BHI 32768
#define OFF_BLO 49152
#define SMEM_BYTES (2 * BUF_STRIDE)

__global__ __launch_bounds__(NTHREADS, 1) void gemm_mma_kernel(
    const float* __restrict__ e0, const float* __restrict__ e1,
    const float* __restrict__ e2, const float* __restrict__ e3,
    const float* __restrict__ p0, const float* __restrict__ p1,
    const float* __restrict__ p2, const float* __restrict__ p3,
    float* __restrict__ out)
{
    extern __shared__ char smem[];
    const uint32_t sb = smem_u32(smem);
    __shared__ int s_loc[128];

    const int tile = blockIdx.y;
    if (tile >= g_total_tiles) return;

    const int cluster = g_tile_c[tile];
    const int m0 = g_tile_m0[tile];
    const int cnt = g_cnt[cluster];
    const int K = c_K[cluster];
    const int n0 = blockIdx.x * 128;
    const float* emb  = cluster == 0 ? e0 : cluster == 1 ? e1 : cluster == 2 ? e2 : e3;
    const float* proj = cluster == 0 ? p0 : cluster == 1 ? p1 : cluster == 2 ? p2 : p3;

    const int tid  = threadIdx.x;
    const int lane = tid & 31;
    const int wid  = tid >> 5;

    for (int i = tid; i < 128; i += NTHREADS) {
        const int r = m0 + i;
        s_loc[i] = (r < cnt) ? g_loc[cluster][r] : -1;
    }
    __syncthreads();

    const int nchunks = (K + 63) >> 6;

    if (wid >= 8) {
        // ---------------- producer warps (4 warps, 128 threads) ----------------
        const int ptid = tid - 256;
        for (int ic = 0; ic < nchunks; ic++) {
            const int k0 = ic << 6;
            const int kc = (K - k0) < 64 ? (K - k0) : 64;
            const int lgn = (kc == 64) ? 3 : 1;
            const int nch = 1 << lgn;
            const int b = ic & 1;
            const uint32_t bo = (uint32_t)b * BUF_STRIDE;

            if (ic >= 2) BAR_SYNC(3 + b);   // wait buffer consumed

            const int tot = 128 * nch;
            for (int ci = ptid; ci < tot; ci += 128) {
                const int r = ci >> lgn;
                const int j = ci & (nch - 1);
                const uint32_t sw = (uint32_t)(r * 128 + j * 16) ^ (uint32_t)((r & 7) << 4);
                const int gl = s_loc[r];
                uint4 hiv, lov;
                if (gl >= 0) {
                    const float* s = emb + (size_t)gl * K + k0 + j * 8;
                    split8(*reinterpret_cast<const float4*>(s),
                           *reinterpret_cast<const float4*>(s + 4), hiv, lov);
                } else {
                    hiv = make_uint4(0, 0, 0, 0);
                    lov = hiv;
                }
                *reinterpret_cast<uint4*>(smem + bo + OFF_AHI + sw) = hiv;
                *reinterpret_cast<uint4*>(smem + bo + OFF_ALO + sw) = lov;
                const float* sB = proj + (size_t)(n0 + r) * K + k0 + j * 8;
                split8(*reinterpret_cast<const float4*>(sB),
                       *reinterpret_cast<const float4*>(sB + 4), hiv, lov);
                *reinterpret_cast<uint4*>(smem + bo + OFF_BHI + sw) = hiv;
                *reinterpret_cast<uint4*>(smem + bo + OFF_BLO + sw) = lov;
            }
            BAR_ARRIVE(1 + b);              // buffer full
        }
        return;
    }

    // ---------------- consumer warps (8 warps: 4 M x 2 N) ----------------
    const int mwarp = (wid & 3) * 32;
    const int nwarp = (wid >> 2) * 64;

    float acc[2][8][4] = {};

    for (int ic = 0; ic < nchunks; ic++) {
        const int k0 = ic << 6;
        const int kc = (K - k0) < 64 ? (K - k0) : 64;
        const int b = ic & 1;
        const uint32_t bo = sb + (uint32_t)b * BUF_STRIDE;

        BAR_SYNC(1 + b);                    // wait buffer full

        const int ksteps = kc >> 4;         // 1 or 4
        for (int ks = 0; ks < ksteps; ks++) {
            uint32_t ah[2][4], al[2][4];
            const int arow = lane & 15;
            const int akb  = ks * 32 + (lane >> 4) * 16;
#pragma unroll
            for (int mt = 0; mt < 2; mt++) {
                const int row = mwarp + mt * 16 + arow;
                ldsm4(ah[mt], swz(bo + OFF_AHI, row, akb));
                ldsm4(al[mt], swz(bo + OFF_ALO, row, akb));
            }
            const int broff = (lane & 7) + ((lane >> 4) << 3);
            const int bkb   = ks * 32 + ((lane >> 3) & 1) * 16;
#pragma unroll
            for (int ng = 0; ng < 4; ng++) {
                uint32_t bh[4], bl[4];
                const int row = nwarp + ng * 16 + broff;
                ldsm4(bh, swz(bo + OFF_BHI, row, bkb));
                ldsm4(bl, swz(bo + OFF_BLO, row, bkb));
#pragma unroll
                for (int mt = 0; mt < 2; mt++) {
                    mma_bf16(acc[mt][2 * ng + 0], ah[mt], bh[0], bh[1]);
                    mma_bf16(acc[mt][2 * ng + 0], ah[mt], bl[0], bl[1]);
                    mma_bf16(acc[mt][2 * ng + 0], al[mt], bh[0], bh[1]);
                    mma_bf16(acc[mt][2 * ng + 1], ah[mt], bh[2], bh[3]);
                    mma_bf16(acc[mt][2 * ng + 1], ah[mt], bl[2], bl[3]);
                    mma_bf16(acc[mt][2 * ng + 1], al[mt], bh[2], bh[3]);
                }
            }
        }
        BAR_ARRIVE(3 + b);                  // buffer consumed
    }

    // epilogue: scale + scatter
#pragma unroll
    for (int mt = 0; mt < 2; mt++) {
        const int r0 = m0 + mwarp + mt * 16 + (lane >> 2);
        const int r1 = r0 + 8;
        float* q0 = nullptr;
        float* q1 = nullptr;
        if (r0 < cnt) q0 = out + (size_t)g_tok[cluster][r0] * D_PROJ + n0 + nwarp + (lane & 3) * 2;
        if (r1 < cnt) q1 = out + (size_t)g_tok[cluster][r1] * D_PROJ + n0 + nwarp + (lane & 3) * 2;
#pragma unroll
        for (int nt = 0; nt < 8; nt++) {
            if (q0) *reinterpret_cast<float2*>(q0 + nt * 8) =
                make_float2(acc[mt][nt][0] * EMB_SCALE, acc[mt][nt][1] * EMB_SCALE);
            if (q1) *reinterpret_cast<float2*>(q1 + nt * 8) =
                make_float2(acc[mt][nt][2] * EMB_SCALE, acc[mt][nt][3] * EMB_SCALE);
        }
    }
}

// ---------------- launch ----------------
extern "C" void kernel_launch(void* const* d_in, const int* in_sizes, int n_in,
                              void* d_out, int out_size) {
    const int* inp = (const int*)d_in[0];
    const float* emb[4];
    const float* proj[4];

    if (n_in >= 9 && in_sizes[2] == 1024 * 1024) {
        for (int i = 0; i < 4; i++) {
            emb[i]  = (const float*)d_in[1 + 2 * i];
            proj[i] = (const float*)d_in[2 + 2 * i];
        }
    } else {
        for (int i = 0; i < 4; i++) {
            emb[i]  = (const float*)d_in[1 + i];
            proj[i] = (const float*)d_in[5 + i];
        }
    }

    float* out = (float*)d_out;
    const int n_tok = in_sizes[0];   // 16384

    cudaFuncSetAttribute(gemm_mma_kernel,
                         cudaFuncAttributeMaxDynamicSharedMemorySize, SMEM_BYTES);

    zero_kernel<<<1, 32>>>();
    bucket_kernel<<<(n_tok + 255) / 256, 256>>>(inp, n_tok);
    plan_kernel<<<1, 128>>>();

    dim3 grid(D_PROJ / 128, MAX_TILES);   // 8 x 136, device-side early exit
    gemm_mma_kernel<<<grid, NTHREADS, SMEM_BYTES>>>(emb[0], emb[1], emb[2], emb[3],
                                                    proj[0], proj[1], proj[2], proj[3],
                                                    out);
}

// round 7
// speedup vs baseline: 1.4975x; 1.4975x over previous
#include <cuda_runtime.h>
#include <cuda_bf16.h>
#include <stdint.h>

#define N_TOKENS_TOTAL 16384
#define D_PROJ 1024
#define EMB_SCALE 32.0f
#define MAX_TILES 136      // sum ceil(cnt_c/128) <= 128+3
#define NTHREADS 256
#define NS 3               // cp.async pipeline stages

// ---------------- scratch ----------------
__device__ int g_cnt[4];
__device__ int g_tok[4][N_TOKENS_TOTAL];
__device__ int g_loc[4][N_TOKENS_TOTAL];
__device__ int g_tile_c[MAX_TILES];
__device__ int g_tile_m0[MAX_TILES];
__device__ int g_total_tiles;

__constant__ int c_K[4] = {1024, 256, 64, 16};

// ---------------- helpers ----------------
__device__ __forceinline__ uint32_t smem_u32(const void* p) {
    uint32_t a;
    asm("{ .reg .u64 t; cvta.to.shared.u64 t, %1; cvt.u32.u64 %0, t; }" : "=r"(a) : "l"(p));
    return a;
}
__device__ __forceinline__ void mma_bf16(float* c, const uint32_t* a,
                                         uint32_t b0, uint32_t b1) {
    asm volatile(
        "mma.sync.aligned.m16n8k16.row.col.f32.bf16.bf16.f32 "
        "{%0,%1,%2,%3}, {%4,%5,%6,%7}, {%8,%9}, {%0,%1,%2,%3};"
        : "+f"(c[0]), "+f"(c[1]), "+f"(c[2]), "+f"(c[3])
        : "r"(a[0]), "r"(a[1]), "r"(a[2]), "r"(a[3]), "r"(b0), "r"(b1));
}
__device__ __forceinline__ void cp16(uint32_t dst, const void* src, int sz) {
    asm volatile("cp.async.cg.shared.global [%0], [%1], 16, %2;"
                 :: "r"(dst), "l"(src), "r"(sz) : "memory");
}
#define CP_COMMIT() asm volatile("cp.async.commit_group;" ::: "memory")
#define CP_WAIT1()  asm volatile("cp.async.wait_group 1;" ::: "memory")

// fp32 smem addressing: rows of 32 floats padded to 128B,
// 16B-granule swizzle: g' = g ^ ((row&3)<<1)  (conflict-free for fragment LDS)
__device__ __forceinline__ uint32_t faddr(uint32_t base, int row, int k) {
    return base + (uint32_t)(row * 128) +
           ((uint32_t)(((k >> 2) ^ ((row & 3) << 1)) << 4)) + (uint32_t)((k & 3) * 4);
}
__device__ __forceinline__ float2 lds2(uint32_t addr) {
    float2 v;
    asm volatile("ld.shared.v2.f32 {%0,%1}, [%2];" : "=f"(v.x), "=f"(v.y) : "r"(addr));
    return v;
}
// float2 -> packed bf16x2 hi + lo
__device__ __forceinline__ void split2(float2 f, uint32_t& hi, uint32_t& lo) {
    __nv_bfloat162 h = __float22bfloat162_rn(f);
    float2 hf = __bfloat1622float2(h);
    float2 r = make_float2(f.x - hf.x, f.y - hf.y);
    __nv_bfloat162 l = __float22bfloat162_rn(r);
    hi = *reinterpret_cast<uint32_t*>(&h);
    lo = *reinterpret_cast<uint32_t*>(&l);
}

// ---------------- small kernels ----------------
__global__ void zero_kernel() {
    if (threadIdx.x < 4) g_cnt[threadIdx.x] = 0;
}
__global__ void bucket_kernel(const int* __restrict__ inp, int n) {
    int t = blockIdx.x * blockDim.x + threadIdx.x;
    if (t >= n) return;
    int v = inp[t];
    int c, l;
    if (v < 20000)       { c = 0; l = 0; }
    else if (v < 40000)  { c = 1; l = 20000; }
    else if (v < 200000) { c = 2; l = 40000; }
    else                 { c = 3; l = 200000; }
    int p = atomicAdd(&g_cnt[c], 1);
    g_tok[c][p] = t;
    g_loc[c][p] = v - l;
}
__global__ void plan_kernel() {
    __shared__ int offs[5];
    if (threadIdx.x == 0) {
        offs[0] = 0;
        for (int c = 0; c < 4; c++) offs[c + 1] = offs[c] + ((g_cnt[c] + 127) >> 7);
        g_total_tiles = offs[4];
    }
    __syncthreads();
    const int total = offs[4];
    for (int i = threadIdx.x; i < total; i += blockDim.x) {
        int c = 0;
        while (i >= offs[c + 1]) c++;
        g_tile_c[i] = c;
        g_tile_m0[i] = (i - offs[c]) << 7;
    }
}

// ---------------- fused cp.async-pipelined GEMM ----------------
// BK=32: stage = A[128][32]f32 (16KB) + B[128][32]f32 (16KB) = 32KB; NS=3 -> 96KB.
#define STG_A 0
#define STG_B 16384
#define STG_STRIDE 32768
#define SMEM_BYTES (NS * STG_STRIDE)

__global__ __launch_bounds__(NTHREADS, 2) void gemm_mma_kernel(
    const float* __restrict__ e0, const float* __restrict__ e1,
    const float* __restrict__ e2, const float* __restrict__ e3,
    const float* __restrict__ p0, const float* __restrict__ p1,
    const float* __restrict__ p2, const float* __restrict__ p3,
    float* __restrict__ out)
{
    extern __shared__ char smem[];
    const uint32_t sb = smem_u32(smem);
    __shared__ int s_loc[128];

    const int tile = blockIdx.y;
    if (tile >= g_total_tiles) return;

    const int cluster = g_tile_c[tile];
    const int m0 = g_tile_m0[tile];
    const int cnt = g_cnt[cluster];
    const int K = c_K[cluster];
    const int n0 = blockIdx.x * 128;
    const float* emb  = cluster == 0 ? e0 : cluster == 1 ? e1 : cluster == 2 ? e2 : e3;
    const float* proj = cluster == 0 ? p0 : cluster == 1 ? p1 : cluster == 2 ? p2 : p3;

    const int tid  = threadIdx.x;
    const int lane = tid & 31;
    const int wid  = tid >> 5;
    const int mwarp = (wid & 3) * 32;
    const int nwarp = (wid >> 2) * 64;

    for (int i = tid; i < 128; i += NTHREADS) {
        const int r = m0 + i;
        s_loc[i] = (r < cnt) ? g_loc[cluster][r] : -1;
    }
    __syncthreads();

    const int nchunks = (K + 31) >> 5;

    // cp.async stage issue: copy chunk ic into buffer ic%NS
    auto issue = [&](int ic) {
        const int k0 = ic << 5;
        const int kc = (K - k0) < 32 ? (K - k0) : 32;   // 32 or 16
        const int lgn = (kc == 32) ? 3 : 2;             // 16B granules per row
        const int ng = 1 << lgn;
        const uint32_t bo = sb + (uint32_t)(ic % NS) * STG_STRIDE;
        const int tot = 128 << lgn;
        for (int ci = tid; ci < tot; ci += NTHREADS) {
            const int row = ci >> lgn;
            const int g = ci & (ng - 1);
            const uint32_t sw = (uint32_t)(row * 128) +
                                ((uint32_t)((g ^ ((row & 3) << 1)) << 4));
            const int gl = s_loc[row];
            const float* srcA = emb + ((gl >= 0 ? (size_t)gl : 0) * K + k0 + g * 4);
            cp16(bo + STG_A + sw, srcA, gl >= 0 ? 16 : 0);
            const float* srcB = proj + ((size_t)(n0 + row) * K + k0 + g * 4);
            cp16(bo + STG_B + sw, srcB, 16);
        }
    };

    // prologue: NS-1 committed groups
    for (int s = 0; s < NS - 1; s++) {
        if (s < nchunks) issue(s);
        CP_COMMIT();
    }

    float acc[2][8][4] = {};

    for (int ic = 0; ic < nchunks; ic++) {
        CP_WAIT1();            // stage ic resident (groups retire in order)
        __syncthreads();       // visible to all warps; prior compute done
        if (ic + NS - 1 < nchunks) issue(ic + NS - 1);
        CP_COMMIT();

        const int k0 = ic << 5;
        const int kc = (K - k0) < 32 ? (K - k0) : 32;
        const uint32_t bo = sb + (uint32_t)(ic % NS) * STG_STRIDE;
        const int ksteps = kc >> 4;            // 2 or 1

        for (int ks = 0; ks < ksteps; ks++) {
            const int kb = ks * 16 + (lane & 3) * 2;
            // A fragments (hi+lo) via direct LDS + split
            uint32_t ah[2][4], al[2][4];
#pragma unroll
            for (int mt = 0; mt < 2; mt++) {
                const int r = mwarp + mt * 16 + (lane >> 2);
                split2(lds2(faddr(bo + STG_A, r,     kb)),     ah[mt][0], al[mt][0]);
                split2(lds2(faddr(bo + STG_A, r + 8, kb)),     ah[mt][1], al[mt][1]);
                split2(lds2(faddr(bo + STG_A, r,     kb + 8)), ah[mt][2], al[mt][2]);
                split2(lds2(faddr(bo + STG_A, r + 8, kb + 8)), ah[mt][3], al[mt][3]);
            }
            // B fragments per n8 tile
#pragma unroll
            for (int nt = 0; nt < 8; nt++) {
                const int r = nwarp + nt * 8 + (lane >> 2);
                uint32_t bh0, bl0, bh1, bl1;
                split2(lds2(faddr(bo + STG_B, r, kb)),     bh0, bl0);
                split2(lds2(faddr(bo + STG_B, r, kb + 8)), bh1, bl1);
#pragma unroll
                for (int mt = 0; mt < 2; mt++) {
                    mma_bf16(acc[mt][nt], ah[mt], bh0, bh1);
                    mma_bf16(acc[mt][nt], ah[mt], bl0, bl1);
                    mma_bf16(acc[mt][nt], al[mt], bh0, bh1);
                }
            }
        }
        __syncthreads();       // compute done before buffer reuse (issued next iter)
    }

    // epilogue: scale + scatter
#pragma unroll
    for (int mt = 0; mt < 2; mt++) {
        const int r0 = m0 + mwarp + mt * 16 + (lane >> 2);
        const int r1 = r0 + 8;
        float* q0 = nullptr;
        float* q1 = nullptr;
        if (r0 < cnt) q0 = out + (size_t)g_tok[cluster][r0] * D_PROJ + n0 + nwarp + (lane & 3) * 2;
        if (r1 < cnt) q1 = out + (size_t)g_tok[cluster][r1] * D_PROJ + n0 + nwarp + (lane & 3) * 2;
#pragma unroll
        for (int nt = 0; nt < 8; nt++) {
            if (q0) *reinterpret_cast<float2*>(q0 + nt * 8) =
                make_float2(acc[mt][nt][0] * EMB_SCALE, acc[mt][nt][1] * EMB_SCALE);
            if (q1) *reinterpret_cast<float2*>(q1 + nt * 8) =
                make_float2(acc[mt][nt][2] * EMB_SCALE, acc[mt][nt][3] * EMB_SCALE);
        }
    }
}

// ---------------- launch ----------------
extern "C" void kernel_launch(void* const* d_in, const int* in_sizes, int n_in,
                              void* d_out, int out_size) {
    const int* inp = (const int*)d_in[0];
    const float* emb[4];
    const float* proj[4];

    if (n_in >= 9 && in_sizes[2] == 1024 * 1024) {
        for (int i = 0; i < 4; i++) {
            emb[i]  = (const float*)d_in[1 + 2 * i];
            proj[i] = (const float*)d_in[2 + 2 * i];
        }
    } else {
        for (int i = 0; i < 4; i++) {
            emb[i]  = (const float*)d_in[1 + i];
            proj[i] = (const float*)d_in[5 + i];
        }
    }

    float* out = (float*)d_out;
    const int n_tok = in_sizes[0];

    cudaFuncSetAttribute(gemm_mma_kernel,
                         cudaFuncAttributeMaxDynamicSharedMemorySize, SMEM_BYTES);

    zero_kernel<<<1, 32>>>();
    bucket_kernel<<<(n_tok + 255) / 256, 256>>>(inp, n_tok);
    plan_kernel<<<1, 128>>>();

    dim3 grid(D_PROJ / 128, MAX_TILES);
    gemm_mma_kernel<<<grid, NTHREADS, SMEM_BYTES>>>(emb[0], emb[1], emb[2], emb[3],
                                                    proj[0], proj[1], proj[2], proj[3],
                                                    out);
}